// round 1
// baseline (speedup 1.0000x reference)
#include <cuda_runtime.h>
#include <cuda_bf16.h>

#define N_NODES 50000
#define N_EDGES 1600000
#define D 64

// ---------------- scratch (device globals; no allocations allowed) ----------
__device__ int   g_cnt[N_NODES];
__device__ int   g_off[N_NODES + 1];
__device__ int   g_cursor[N_NODES];
__device__ int   g_csr_dst[N_EDGES];
__device__ float g_csr_w[N_EDGES];
__device__ float g_agg[N_NODES * D];    // aggregation buffer (reused per layer)
__device__ float g_h[N_NODES * D];      // layer-1 output
__device__ float g_Wt[2][128 * 64];     // transposed weights: [k][j]

// ---------------- CSR build -------------------------------------------------
__global__ void k_zero_cnt() {
    int i = blockIdx.x * blockDim.x + threadIdx.x;
    if (i < N_NODES) g_cnt[i] = 0;
}

__global__ void k_count(const int* __restrict__ src) {
    int e = blockIdx.x * blockDim.x + threadIdx.x;
    if (e < N_EDGES) atomicAdd(&g_cnt[src[e]], 1);
}

// single-block exclusive scan over 50000 counts (Hillis-Steele per 1024 chunk)
__global__ void k_scan() {
    __shared__ int sm[1024];
    const int tid = threadIdx.x;
    int running = 0;
    for (int base = 0; base < N_NODES; base += 1024) {
        int i = base + tid;
        int v = (i < N_NODES) ? g_cnt[i] : 0;
        __syncthreads();
        sm[tid] = v;
        __syncthreads();
        #pragma unroll
        for (int d = 1; d < 1024; d <<= 1) {
            int y = (tid >= d) ? sm[tid - d] : 0;
            __syncthreads();
            if (tid >= d) sm[tid] += y;
            __syncthreads();
        }
        int incl  = sm[tid];
        int total = sm[1023];
        if (i < N_NODES) {
            int excl = running + incl - v;
            g_off[i]    = excl;
            g_cursor[i] = excl;
        }
        running += total;
    }
    if (tid == 0) g_off[N_NODES] = running;
}

__global__ void k_fill(const int* __restrict__ src, const int* __restrict__ dst,
                       const float* __restrict__ ew) {
    int e = blockIdx.x * blockDim.x + threadIdx.x;
    if (e < N_EDGES) {
        int p = atomicAdd(&g_cursor[src[e]], 1);
        g_csr_dst[p] = dst[e];
        g_csr_w[p]   = ew[e];
    }
}

// ---------------- weight transpose: g_Wt[which][k*64+j] = W[j*128+k] --------
__global__ void k_transpose(const float* __restrict__ W, int which) {
    int t = blockIdx.x * blockDim.x + threadIdx.x;
    if (t < 64 * 128) {
        int j = t >> 7, k = t & 127;
        g_Wt[which][k * 64 + j] = W[t];
    }
}

// ---------------- pull-based aggregation (one warp per node, no atomics) ----
__global__ void __launch_bounds__(256) k_aggregate(const float* xin_ext) {
    const float* __restrict__ xin = xin_ext ? xin_ext : g_h;
    int warp = (blockIdx.x * blockDim.x + threadIdx.x) >> 5;
    int lane = threadIdx.x & 31;
    if (warp >= N_NODES) return;

    int beg = g_off[warp];
    int end = g_off[warp + 1];

    float2 a0 = make_float2(0.f, 0.f);
    float2 a1 = make_float2(0.f, 0.f);
    int i = beg;
    for (; i + 2 <= end; i += 2) {
        int   d0 = g_csr_dst[i];
        int   d1 = g_csr_dst[i + 1];
        float w0 = g_csr_w[i];
        float w1 = g_csr_w[i + 1];
        float2 v0 = __ldg((const float2*)(xin + (size_t)d0 * D) + lane);
        float2 v1 = __ldg((const float2*)(xin + (size_t)d1 * D) + lane);
        a0.x += v0.x * w0; a0.y += v0.y * w0;
        a1.x += v1.x * w1; a1.y += v1.y * w1;
    }
    if (i < end) {
        int   d0 = g_csr_dst[i];
        float w0 = g_csr_w[i];
        float2 v0 = __ldg((const float2*)(xin + (size_t)d0 * D) + lane);
        a0.x += v0.x * w0; a0.y += v0.y * w0;
    }
    float2 acc = make_float2(a0.x + a1.x, a0.y + a1.y);
    ((float2*)(g_agg + (size_t)warp * D))[lane] = acc;
}

// ---------------- fused concat + GEMM + bias + relu -------------------------
// out[n][j] = relu( sum_k<64 x[n][k]*W[j][k] + sum_k<64 (agg[n][k]/max(cnt,1))*W[j][64+k] + b[j] )
// tile: 32 nodes x 64 cols per block (256 threads, 8 outputs each: 2 nodes x 4 cols)
__global__ void __launch_bounds__(256) k_gemm(const float* xin_ext, int whichW,
                                              const float* __restrict__ bias,
                                              float* out_ext) {
    const float* __restrict__ xin = xin_ext ? xin_ext : g_h;
    float* __restrict__ out = out_ext ? out_ext : g_h;

    __shared__ __align__(16) float Wsm[128][64];   // [k][j], 32 KB
    __shared__ float rows[128][32];                // [k][node], 16 KB

    const int tid = threadIdx.x;
    const int n0  = blockIdx.x * 32;

    // load transposed W: coalesced gmem, conflict-free STS
    const float* __restrict__ Wt = g_Wt[whichW];
    #pragma unroll
    for (int t = tid; t < 128 * 64; t += 256)
        ((float*)Wsm)[t] = Wt[t];

    // load row tile: concat(x, agg/cnt) transposed into [k][node]
    for (int t = tid; t < 32 * 32; t += 256) {      // 32 nodes x 32 float4-chunks
        int node = t & 31;
        int kc   = t >> 5;                           // 0..31 (k = 4*kc)
        int n    = n0 + node;
        float4 v = make_float4(0.f, 0.f, 0.f, 0.f);
        if (n < N_NODES) {
            if (kc < 16) {
                v = __ldg((const float4*)(xin + (size_t)n * D) + kc);
            } else {
                float inv = 1.0f / fmaxf((float)g_cnt[n], 1.0f);
                float4 a  = __ldg((const float4*)(g_agg + (size_t)n * D) + (kc - 16));
                v = make_float4(a.x * inv, a.y * inv, a.z * inv, a.w * inv);
            }
        }
        int k = kc * 4;
        rows[k + 0][node] = v.x;
        rows[k + 1][node] = v.y;
        rows[k + 2][node] = v.z;
        rows[k + 3][node] = v.w;
    }
    __syncthreads();

    const int cg = tid & 15;        // column group: j = 4*cg .. 4*cg+3
    const int ng = tid >> 4;        // node group:   n = 2*ng, 2*ng+1
    const int j0 = cg * 4;
    const int na = 2 * ng;
    const int nb = na + 1;

    float acc00 = 0.f, acc01 = 0.f, acc02 = 0.f, acc03 = 0.f;
    float acc10 = 0.f, acc11 = 0.f, acc12 = 0.f, acc13 = 0.f;

    #pragma unroll 8
    for (int k = 0; k < 128; k++) {
        float4 w4 = *(const float4*)&Wsm[k][j0];
        float  ra = rows[k][na];
        float  rb = rows[k][nb];
        acc00 += ra * w4.x; acc01 += ra * w4.y; acc02 += ra * w4.z; acc03 += ra * w4.w;
        acc10 += rb * w4.x; acc11 += rb * w4.y; acc12 += rb * w4.z; acc13 += rb * w4.w;
    }

    float b0 = __ldg(&bias[j0 + 0]);
    float b1 = __ldg(&bias[j0 + 1]);
    float b2 = __ldg(&bias[j0 + 2]);
    float b3 = __ldg(&bias[j0 + 3]);

    int n = n0 + na;
    if (n < N_NODES) {
        float* o = out + (size_t)n * D + j0;
        o[0] = fmaxf(acc00 + b0, 0.f);
        o[1] = fmaxf(acc01 + b1, 0.f);
        o[2] = fmaxf(acc02 + b2, 0.f);
        o[3] = fmaxf(acc03 + b3, 0.f);
    }
    n = n0 + nb;
    if (n < N_NODES) {
        float* o = out + (size_t)n * D + j0;
        o[0] = fmaxf(acc10 + b0, 0.f);
        o[1] = fmaxf(acc11 + b1, 0.f);
        o[2] = fmaxf(acc12 + b2, 0.f);
        o[3] = fmaxf(acc13 + b3, 0.f);
    }
}

// ---------------- launch -----------------------------------------------------
extern "C" void kernel_launch(void* const* d_in, const int* in_sizes, int n_in,
                              void* d_out, int out_size) {
    const float* x  = (const float*)d_in[0];
    const int*   ei = (const int*)  d_in[1];
    const float* ew = (const float*)d_in[2];
    const float* W1 = (const float*)d_in[3];
    const float* b1 = (const float*)d_in[4];
    const float* W2 = (const float*)d_in[5];
    const float* b2 = (const float*)d_in[6];
    float* out = (float*)d_out;

    const int* src = ei;
    const int* dst = ei + N_EDGES;

    // CSR build (shared by both layers)
    k_zero_cnt<<<(N_NODES + 255) / 256, 256>>>();
    k_count   <<<(N_EDGES + 255) / 256, 256>>>(src);
    k_scan    <<<1, 1024>>>();
    k_fill    <<<(N_EDGES + 255) / 256, 256>>>(src, dst, ew);

    // weight transposes
    k_transpose<<<32, 256>>>(W1, 0);
    k_transpose<<<32, 256>>>(W2, 1);

    // layer 1: aggregate(x) -> g_agg ; gemm(x, g_agg) -> g_h (relu)
    k_aggregate<<<(N_NODES * 32 + 255) / 256, 256>>>(x);
    k_gemm     <<<(N_NODES + 31) / 32, 256>>>(x, 0, b1, nullptr);

    // layer 2: aggregate(g_h) -> g_agg ; gemm(g_h, g_agg) -> out (relu)
    k_aggregate<<<(N_NODES * 32 + 255) / 256, 256>>>(nullptr);
    k_gemm     <<<(N_NODES + 31) / 32, 256>>>(nullptr, 1, b2, out);
}

// round 2
// speedup vs baseline: 1.3404x; 1.3404x over previous
#include <cuda_runtime.h>
#include <cuda_fp16.h>
#include <cuda_bf16.h>

#define N_NODES 50000
#define N_EDGES 1600000
#define D 64

// ---------------- scratch (device globals; no allocations allowed) ----------
__device__ int    g_cnt[N_NODES];
__device__ int    g_off[N_NODES];
__device__ int    g_cursor[N_NODES];
__device__ int    g_total;
__device__ int2   g_csr[N_EDGES];          // {dst, weight_bits}
__device__ float  g_agg[N_NODES * D];      // aggregation buffer (fp32)
__device__ float  g_h[N_NODES * D];        // layer-1 output (fp32, for GEMM x-part)
__device__ __half g_x16[N_NODES * D];      // fp16 mirror of x   (gather source L1)
__device__ __half g_h16[N_NODES * D];      // fp16 mirror of h   (gather source L2)
__device__ float  g_Wt[2][128 * 64];       // transposed weights: [k][j]

// ---------------- CSR build -------------------------------------------------
__global__ void k_zero() {
    int i = blockIdx.x * blockDim.x + threadIdx.x;
    if (i < N_NODES) g_cnt[i] = 0;
    if (i == 0) g_total = 0;
}

__global__ void k_count(const int* __restrict__ src) {
    int e = blockIdx.x * blockDim.x + threadIdx.x;
    if (e < N_EDGES) atomicAdd(&g_cnt[src[e]], 1);
}

// region assignment: order-free "scan" via single global counter.
// uniform-address atomicAdd -> REDUX warp aggregation (cheap).
__global__ void k_assign() {
    int i = blockIdx.x * blockDim.x + threadIdx.x;
    if (i < N_NODES) {
        int c = g_cnt[i];
        int p = atomicAdd(&g_total, c);
        g_off[i]    = p;
        g_cursor[i] = p;
    }
}

__global__ void k_fill(const int* __restrict__ src, const int* __restrict__ dst,
                       const float* __restrict__ ew) {
    int e = blockIdx.x * blockDim.x + threadIdx.x;
    if (e < N_EDGES) {
        int p = atomicAdd(&g_cursor[src[e]], 1);
        g_csr[p] = make_int2(dst[e], __float_as_int(ew[e]));
    }
}

// ---------------- weight transpose: g_Wt[which][k*64+j] = W[j*128+k] --------
__global__ void k_transpose(const float* __restrict__ W, int which) {
    int t = blockIdx.x * blockDim.x + threadIdx.x;
    if (t < 64 * 128) {
        int j = t >> 7, k = t & 127;
        g_Wt[which][k * 64 + j] = W[t];
    }
}

// ---------------- fp32 -> fp16 feature mirror -------------------------------
__global__ void k_tohalf(const float* __restrict__ x, __half* __restrict__ o) {
    int i = blockIdx.x * blockDim.x + threadIdx.x;        // one float4 per thread
    if (i < N_NODES * D / 4) {
        float4 v = __ldg((const float4*)x + i);
        __half2 h0 = __floats2half2_rn(v.x, v.y);
        __half2 h1 = __floats2half2_rn(v.z, v.w);
        uint2 u;
        u.x = reinterpret_cast<const unsigned&>(h0);
        u.y = reinterpret_cast<const unsigned&>(h1);
        ((uint2*)o)[i] = u;
    }
}

// ---------------- pull-based aggregation (one warp per node, no atomics) ----
// gathers fp16 feature rows (128 B/edge), accumulates fp32
__global__ void __launch_bounds__(256) k_aggregate(const __half* __restrict__ xin16) {
    int node = (blockIdx.x * blockDim.x + threadIdx.x) >> 5;
    int lane = threadIdx.x & 31;
    if (node >= N_NODES) return;

    const int beg = g_off[node];
    const int n   = g_cnt[node];
    const int2* __restrict__ csr = g_csr + beg;

    float2 a0 = make_float2(0.f, 0.f);
    float2 a1 = make_float2(0.f, 0.f);
    float2 a2 = make_float2(0.f, 0.f);
    float2 a3 = make_float2(0.f, 0.f);

    int i = 0;
    for (; i + 4 <= n; i += 4) {
        int2 e0 = csr[i], e1 = csr[i + 1], e2 = csr[i + 2], e3 = csr[i + 3];
        __half2 h0 = __ldg((const __half2*)(xin16 + (size_t)e0.x * D) + lane);
        __half2 h1 = __ldg((const __half2*)(xin16 + (size_t)e1.x * D) + lane);
        __half2 h2 = __ldg((const __half2*)(xin16 + (size_t)e2.x * D) + lane);
        __half2 h3 = __ldg((const __half2*)(xin16 + (size_t)e3.x * D) + lane);
        float w0 = __int_as_float(e0.y), w1 = __int_as_float(e1.y);
        float w2 = __int_as_float(e2.y), w3 = __int_as_float(e3.y);
        float2 v0 = __half22float2(h0), v1 = __half22float2(h1);
        float2 v2 = __half22float2(h2), v3 = __half22float2(h3);
        a0.x += v0.x * w0; a0.y += v0.y * w0;
        a1.x += v1.x * w1; a1.y += v1.y * w1;
        a2.x += v2.x * w2; a2.y += v2.y * w2;
        a3.x += v3.x * w3; a3.y += v3.y * w3;
    }
    for (; i < n; i++) {
        int2 e0 = csr[i];
        __half2 h0 = __ldg((const __half2*)(xin16 + (size_t)e0.x * D) + lane);
        float w0 = __int_as_float(e0.y);
        float2 v0 = __half22float2(h0);
        a0.x += v0.x * w0; a0.y += v0.y * w0;
    }
    float2 acc = make_float2(a0.x + a1.x + a2.x + a3.x,
                             a0.y + a1.y + a2.y + a3.y);
    ((float2*)(g_agg + (size_t)node * D))[lane] = acc;
}

// ---------------- fused concat + GEMM + bias + relu -------------------------
// out[n][j] = relu( sum_k<64 x[n][k]*W[j][k]
//                 + sum_k<64 (agg[n][k]/max(cnt,1))*W[j][64+k] + b[j] )
// tile: 32 nodes x 64 cols per block (256 threads, 8 outputs each)
__global__ void __launch_bounds__(256) k_gemm(const float* __restrict__ xin, int whichW,
                                              const float* __restrict__ bias,
                                              float* __restrict__ out,
                                              __half* __restrict__ out16) {
    __shared__ __align__(16) float Wsm[128][64];   // [k][j], 32 KB
    __shared__ __align__(8)  float rows[128][32];  // [k][node], 16 KB

    const int tid = threadIdx.x;
    const int n0  = blockIdx.x * 32;

    // load transposed W: coalesced gmem, conflict-free STS
    const float* __restrict__ Wt = g_Wt[whichW];
    #pragma unroll
    for (int t = tid; t < 128 * 64; t += 256)
        ((float*)Wsm)[t] = Wt[t];

    // load row tile: concat(x, agg/cnt) transposed into [k][node]
    for (int t = tid; t < 32 * 32; t += 256) {      // 32 nodes x 32 float4-chunks
        int node = t & 31;
        int kc   = t >> 5;                           // k = 4*kc
        int n    = n0 + node;
        float4 v = make_float4(0.f, 0.f, 0.f, 0.f);
        if (n < N_NODES) {
            if (kc < 16) {
                v = __ldg((const float4*)(xin + (size_t)n * D) + kc);
            } else {
                float inv = 1.0f / fmaxf((float)g_cnt[n], 1.0f);
                float4 a  = __ldg((const float4*)(g_agg + (size_t)n * D) + (kc - 16));
                v = make_float4(a.x * inv, a.y * inv, a.z * inv, a.w * inv);
            }
        }
        int k = kc * 4;
        rows[k + 0][node] = v.x;
        rows[k + 1][node] = v.y;
        rows[k + 2][node] = v.z;
        rows[k + 3][node] = v.w;
    }
    __syncthreads();

    const int cg = tid & 15;        // column group: j = 4*cg .. 4*cg+3
    const int ng = tid >> 4;        // node group:   n = 2*ng, 2*ng+1
    const int j0 = cg * 4;
    const int na = 2 * ng;

    float acc00 = 0.f, acc01 = 0.f, acc02 = 0.f, acc03 = 0.f;
    float acc10 = 0.f, acc11 = 0.f, acc12 = 0.f, acc13 = 0.f;

    #pragma unroll 8
    for (int k = 0; k < 128; k++) {
        float4 w4 = *(const float4*)&Wsm[k][j0];
        float2 r  = *(const float2*)&rows[k][na];   // nodes na, na+1 in one LDS.64
        acc00 += r.x * w4.x; acc01 += r.x * w4.y; acc02 += r.x * w4.z; acc03 += r.x * w4.w;
        acc10 += r.y * w4.x; acc11 += r.y * w4.y; acc12 += r.y * w4.z; acc13 += r.y * w4.w;
    }

    float b0 = __ldg(&bias[j0 + 0]);
    float b1 = __ldg(&bias[j0 + 1]);
    float b2 = __ldg(&bias[j0 + 2]);
    float b3 = __ldg(&bias[j0 + 3]);

    #pragma unroll
    for (int r = 0; r < 2; r++) {
        int n = n0 + na + r;
        if (n >= N_NODES) continue;
        float o0 = fmaxf((r ? acc10 : acc00) + b0, 0.f);
        float o1 = fmaxf((r ? acc11 : acc01) + b1, 0.f);
        float o2 = fmaxf((r ? acc12 : acc02) + b2, 0.f);
        float o3 = fmaxf((r ? acc13 : acc03) + b3, 0.f);
        float* o = out + (size_t)n * D + j0;
        o[0] = o0; o[1] = o1; o[2] = o2; o[3] = o3;
        if (out16) {
            __half2 h0 = __floats2half2_rn(o0, o1);
            __half2 h1 = __floats2half2_rn(o2, o3);
            uint2 u;
            u.x = reinterpret_cast<const unsigned&>(h0);
            u.y = reinterpret_cast<const unsigned&>(h1);
            *(uint2*)(out16 + (size_t)n * D + j0) = u;
        }
    }
}

// ---------------- launch -----------------------------------------------------
extern "C" void kernel_launch(void* const* d_in, const int* in_sizes, int n_in,
                              void* d_out, int out_size) {
    const float* x  = (const float*)d_in[0];
    const int*   ei = (const int*)  d_in[1];
    const float* ew = (const float*)d_in[2];
    const float* W1 = (const float*)d_in[3];
    const float* b1 = (const float*)d_in[4];
    const float* W2 = (const float*)d_in[5];
    const float* b2 = (const float*)d_in[6];
    float* out = (float*)d_out;

    const int* src = ei;
    const int* dst = ei + N_EDGES;

    __half* x16 = nullptr; cudaGetSymbolAddress((void**)&x16, g_x16);
    __half* h16 = nullptr; cudaGetSymbolAddress((void**)&h16, g_h16);
    float*  h   = nullptr; cudaGetSymbolAddress((void**)&h,   g_h);

    // CSR build (shared by both layers); offsets via order-free atomic assign
    k_zero  <<<(N_NODES + 255) / 256, 256>>>();
    k_count <<<(N_EDGES + 255) / 256, 256>>>(src);
    k_assign<<<(N_NODES + 255) / 256, 256>>>();
    k_fill  <<<(N_EDGES + 255) / 256, 256>>>(src, dst, ew);

    // weight transposes + fp16 mirror of x
    k_transpose<<<32, 256>>>(W1, 0);
    k_transpose<<<32, 256>>>(W2, 1);
    k_tohalf<<<(N_NODES * D / 4 + 255) / 256, 256>>>(x, x16);

    // layer 1: aggregate(x16) -> g_agg ; gemm(x, g_agg) -> g_h (+ g_h16)
    k_aggregate<<<(N_NODES * 32 + 255) / 256, 256>>>(x16);
    k_gemm     <<<(N_NODES + 31) / 32, 256>>>(x, 0, b1, h, h16);

    // layer 2: aggregate(g_h16) -> g_agg ; gemm(g_h, g_agg) -> out
    k_aggregate<<<(N_NODES * 32 + 255) / 256, 256>>>(h16);
    k_gemm     <<<(N_NODES + 31) / 32, 256>>>(h, 1, b2, out, nullptr);
}

// round 4
// speedup vs baseline: 2.0391x; 1.5213x over previous
#include <cuda_runtime.h>
#include <cuda_fp16.h>
#include <cuda_bf16.h>
#include <cstdint>

#define N_NODES 50000
#define N_EDGES 1600000
#define D 64

// ==================== scratch (device globals) ====================
__device__ int    g_cnt[N_NODES];
__device__ int    g_off[N_NODES];
__device__ int    g_cursor[N_NODES];
__device__ int    g_total;
__device__ int2   g_csr[N_EDGES];                 // {dst, weight_bits}
__device__ __align__(16) __half g_x16[N_NODES * D];
__device__ __align__(16) __half g_h16[N_NODES * D];
__device__ __align__(16) __half g_agg16[N_NODES * D];     // agg/cnt, fp16
__device__ __align__(16) uint2  g_Bfrag[2 * 8 * 8 * 32];  // mma-layout B fragments

// ==================== CSR build ====================
__global__ void k_count(const int* __restrict__ src) {
    int e4 = blockIdx.x * blockDim.x + threadIdx.x;
    if (e4 < N_EDGES / 4) {
        int4 s = __ldg((const int4*)src + e4);
        atomicAdd(&g_cnt[s.x], 1);
        atomicAdd(&g_cnt[s.y], 1);
        atomicAdd(&g_cnt[s.z], 1);
        atomicAdd(&g_cnt[s.w], 1);
    }
}

__global__ void k_assign() {   // order-free offsets via one global counter
    int i = blockIdx.x * blockDim.x + threadIdx.x;
    if (i < N_NODES) {
        int c = g_cnt[i];
        int p = atomicAdd(&g_total, c);
        g_off[i]    = p;
        g_cursor[i] = p;
    }
}

__global__ void k_fill(const int* __restrict__ src, const int* __restrict__ dst,
                       const float* __restrict__ ew) {
    int e4 = blockIdx.x * blockDim.x + threadIdx.x;
    if (e4 < N_EDGES / 4) {
        int4   s = __ldg((const int4*)src + e4);
        int4   d = __ldg((const int4*)dst + e4);
        float4 w = __ldg((const float4*)ew + e4);
        int p;
        p = atomicAdd(&g_cursor[s.x], 1); g_csr[p] = make_int2(d.x, __float_as_int(w.x));
        p = atomicAdd(&g_cursor[s.y], 1); g_csr[p] = make_int2(d.y, __float_as_int(w.y));
        p = atomicAdd(&g_cursor[s.z], 1); g_csr[p] = make_int2(d.z, __float_as_int(w.z));
        p = atomicAdd(&g_cursor[s.w], 1); g_csr[p] = make_int2(d.w, __float_as_int(w.w));
    }
}

// ==================== prep: x16 mirror + mma-layout B fragments ====================
// B[k][j] = W[j][k].  Fragment (m16n8k16 .row.col): for lane l (grp=l>>2,q=l&3),
//   b0 = half2(W[j][k0], W[j][k0+1]),  b1 = half2(W[j][k0+8], W[j][k0+9])
//   with j = jt*8+grp, k0 = kt*16+q*2.
#define XBLOCKS ((N_NODES * D / 4 + 255) / 256)
__global__ void k_prep(const float* __restrict__ x,
                       const float* __restrict__ W1, const float* __restrict__ W2) {
    int b = blockIdx.x;
    if (b < XBLOCKS) {
        int i = b * 256 + threadIdx.x;
        if (i < N_NODES * D / 4) {
            float4 v = __ldg((const float4*)x + i);
            __half2 h0 = __floats2half2_rn(v.x, v.y);
            __half2 h1 = __floats2half2_rn(v.z, v.w);
            uint2 u;
            u.x = reinterpret_cast<const unsigned&>(h0);
            u.y = reinterpret_cast<const unsigned&>(h1);
            ((uint2*)g_x16)[i] = u;
        }
    } else {
        int t = (b - XBLOCKS) * 256 + threadIdx.x;      // 0..4095
        if (t < 2 * 8 * 8 * 32) {
            int l    = t >> 11;
            int rem  = t & 2047;
            int kt   = rem >> 8;
            int jt   = (rem >> 5) & 7;
            int lane = rem & 31;
            int grp = lane >> 2, q = lane & 3;
            int j  = jt * 8 + grp;
            int k0 = kt * 16 + q * 2;
            const float* W = l ? W2 : W1;
            __half2 h0 = __floats2half2_rn(W[j * 128 + k0],     W[j * 128 + k0 + 1]);
            __half2 h1 = __floats2half2_rn(W[j * 128 + k0 + 8], W[j * 128 + k0 + 9]);
            uint2 u;
            u.x = reinterpret_cast<const unsigned&>(h0);
            u.y = reinterpret_cast<const unsigned&>(h1);
            g_Bfrag[t] = u;
        }
    }
}

// ==================== pull aggregation (1 warp/node), fp16 out with /cnt fused ====
__global__ void __launch_bounds__(256) k_aggregate(const __half* __restrict__ xin16) {
    int node = (blockIdx.x * blockDim.x + threadIdx.x) >> 5;
    int lane = threadIdx.x & 31;
    if (node >= N_NODES) return;

    const int beg = g_off[node];
    const int n   = g_cnt[node];
    const int2* __restrict__ csr = g_csr + beg;

    float2 a0 = make_float2(0.f, 0.f), a1 = make_float2(0.f, 0.f);
    float2 a2 = make_float2(0.f, 0.f), a3 = make_float2(0.f, 0.f);

    int i = 0;
    for (; i + 4 <= n; i += 4) {
        int2 e0 = csr[i], e1 = csr[i + 1], e2 = csr[i + 2], e3 = csr[i + 3];
        __half2 h0 = __ldg((const __half2*)(xin16 + (size_t)e0.x * D) + lane);
        __half2 h1 = __ldg((const __half2*)(xin16 + (size_t)e1.x * D) + lane);
        __half2 h2 = __ldg((const __half2*)(xin16 + (size_t)e2.x * D) + lane);
        __half2 h3 = __ldg((const __half2*)(xin16 + (size_t)e3.x * D) + lane);
        float w0 = __int_as_float(e0.y), w1 = __int_as_float(e1.y);
        float w2 = __int_as_float(e2.y), w3 = __int_as_float(e3.y);
        float2 v0 = __half22float2(h0), v1 = __half22float2(h1);
        float2 v2 = __half22float2(h2), v3 = __half22float2(h3);
        a0.x += v0.x * w0; a0.y += v0.y * w0;
        a1.x += v1.x * w1; a1.y += v1.y * w1;
        a2.x += v2.x * w2; a2.y += v2.y * w2;
        a3.x += v3.x * w3; a3.y += v3.y * w3;
    }
    for (; i < n; i++) {
        int2 e0 = csr[i];
        __half2 h0 = __ldg((const __half2*)(xin16 + (size_t)e0.x * D) + lane);
        float w0 = __int_as_float(e0.y);
        float2 v0 = __half22float2(h0);
        a0.x += v0.x * w0; a0.y += v0.y * w0;
    }
    float inv = 1.0f / fmaxf((float)n, 1.0f);
    __half2 hv = __floats2half2_rn((a0.x + a1.x + a2.x + a3.x) * inv,
                                   (a0.y + a1.y + a2.y + a3.y) * inv);
    ((uint32_t*)(g_agg16 + (size_t)node * D))[lane] = reinterpret_cast<const unsigned&>(hv);
}

// ==================== HMMA GEMM: mma.sync m16n8k16, no smem ====================
// out[n][j] = relu( [x16[n] | agg16[n]] (fp16, K=128) @ W^T (fp16) + b[j] ), fp32 accum
// CTA = 256 threads = 8 warps; each warp: 16 nodes x 64 cols (8 j-tiles, 8 k-tiles)
__global__ void __launch_bounds__(256) k_gemm_mma(
        const __half* __restrict__ xin16, const __half* __restrict__ agg16,
        int wl, const float* __restrict__ bias,
        float* __restrict__ out32, __half* __restrict__ out16) {
    const int tid  = threadIdx.x;
    const int warp = tid >> 5, lane = tid & 31;
    const int grp  = lane >> 2, q = lane & 3;

    const int r0 = blockIdx.x * 128 + warp * 16 + grp;   // rows r0 and r0+8
    const int r0c = min(r0,     N_NODES - 1);
    const int r1c = min(r0 + 8, N_NODES - 1);

    const uint2* __restrict__ Bf = g_Bfrag + wl * (8 * 8 * 32);

    float c[8][4];
    #pragma unroll
    for (int jt = 0; jt < 8; jt++)
        c[jt][0] = c[jt][1] = c[jt][2] = c[jt][3] = 0.f;

    #pragma unroll
    for (int kt = 0; kt < 8; kt++) {
        const int kc = kt * 16 + q * 2;
        const __half* __restrict__ s = (kc < 64) ? xin16 : agg16;
        const int cc = kc & 63;
        uint32_t a0 = __ldg((const uint32_t*)(s + (size_t)r0c * D + cc));
        uint32_t a1 = __ldg((const uint32_t*)(s + (size_t)r1c * D + cc));
        uint32_t a2 = __ldg((const uint32_t*)(s + (size_t)r0c * D + cc + 8));
        uint32_t a3 = __ldg((const uint32_t*)(s + (size_t)r1c * D + cc + 8));
        #pragma unroll
        for (int jt = 0; jt < 8; jt++) {
            uint2 b = __ldg(Bf + ((kt * 8 + jt) * 32 + lane));
            asm volatile(
                "mma.sync.aligned.m16n8k16.row.col.f32.f16.f16.f32 "
                "{%0,%1,%2,%3}, {%4,%5,%6,%7}, {%8,%9}, {%0,%1,%2,%3};"
                : "+f"(c[jt][0]), "+f"(c[jt][1]), "+f"(c[jt][2]), "+f"(c[jt][3])
                : "r"(a0), "r"(a1), "r"(a2), "r"(a3), "r"(b.x), "r"(b.y));
        }
    }

    const bool w0 = (r0     < N_NODES);
    const bool w1 = (r0 + 8 < N_NODES);
    #pragma unroll
    for (int jt = 0; jt < 8; jt++) {
        const int j0 = jt * 8 + q * 2;
        float2 bb = __ldg((const float2*)(bias + j0));
        float v00 = fmaxf(c[jt][0] + bb.x, 0.f);
        float v01 = fmaxf(c[jt][1] + bb.y, 0.f);
        float v10 = fmaxf(c[jt][2] + bb.x, 0.f);
        float v11 = fmaxf(c[jt][3] + bb.y, 0.f);
        if (out16) {
            if (w0) {
                __half2 h = __floats2half2_rn(v00, v01);
                *(uint32_t*)(out16 + (size_t)r0 * D + j0) = reinterpret_cast<const unsigned&>(h);
            }
            if (w1) {
                __half2 h = __floats2half2_rn(v10, v11);
                *(uint32_t*)(out16 + (size_t)(r0 + 8) * D + j0) = reinterpret_cast<const unsigned&>(h);
            }
        } else {
            if (w0) *(float2*)(out32 + (size_t)r0 * D + j0)       = make_float2(v00, v01);
            if (w1) *(float2*)(out32 + (size_t)(r0 + 8) * D + j0) = make_float2(v10, v11);
        }
    }
}

// ==================== launch ====================
extern "C" void kernel_launch(void* const* d_in, const int* in_sizes, int n_in,
                              void* d_out, int out_size) {
    const float* x  = (const float*)d_in[0];
    const int*   ei = (const int*)  d_in[1];
    const float* ew = (const float*)d_in[2];
    const float* W1 = (const float*)d_in[3];
    const float* b1 = (const float*)d_in[4];
    const float* W2 = (const float*)d_in[5];
    const float* b2 = (const float*)d_in[6];
    float* out = (float*)d_out;

    const int* src = ei;
    const int* dst = ei + N_EDGES;

    void *p_cnt, *p_total, *p_x16, *p_h16, *p_agg16;
    cudaGetSymbolAddress(&p_cnt,   g_cnt);
    cudaGetSymbolAddress(&p_total, g_total);
    cudaGetSymbolAddress(&p_x16,   g_x16);
    cudaGetSymbolAddress(&p_h16,   g_h16);
    cudaGetSymbolAddress(&p_agg16, g_agg16);
    __half* x16   = (__half*)p_x16;
    __half* h16   = (__half*)p_h16;
    __half* agg16 = (__half*)p_agg16;

    cudaMemsetAsync(p_cnt,   0, N_NODES * sizeof(int));
    cudaMemsetAsync(p_total, 0, sizeof(int));

    // CSR build
    k_count <<<(N_EDGES / 4 + 255) / 256, 256>>>(src);
    k_assign<<<(N_NODES + 255) / 256, 256>>>();
    k_fill  <<<(N_EDGES / 4 + 255) / 256, 256>>>(src, dst, ew);

    // x fp16 mirror + mma-layout fp16 B fragments
    k_prep<<<XBLOCKS + 16, 256>>>(x, W1, W2);

    const int gemm_grid = (N_NODES + 127) / 128;

    // layer 1
    k_aggregate<<<(N_NODES * 32 + 255) / 256, 256>>>(x16);
    k_gemm_mma <<<gemm_grid, 256>>>(x16, agg16, 0, b1, nullptr, h16);

    // layer 2
    k_aggregate<<<(N_NODES * 32 + 255) / 256, 256>>>(h16);
    k_gemm_mma <<<gemm_grid, 256>>>(h16, agg16, 1, b2, out, nullptr);
}

// round 5
// speedup vs baseline: 2.0396x; 1.0003x over previous
#include <cuda_runtime.h>
#include <cuda_fp16.h>
#include <cuda_bf16.h>
#include <cstdint>

#define N_NODES 50000
#define N_EDGES 1600000
#define D 64

// ==================== scratch (device globals) ====================
__device__ int    g_cnt[N_NODES];
__device__ int    g_off[N_NODES];
__device__ int    g_cursor[N_NODES];
__device__ int    g_total;
__device__ int2   g_csr[N_EDGES];                 // {dst, weight_bits}
__device__ __align__(16) __half g_x16[N_NODES * D];
__device__ __align__(16) __half g_h16[N_NODES * D];
__device__ __align__(16) __half g_agg16[N_NODES * D];     // agg/cnt, fp16
__device__ __align__(16) uint2  g_Bfrag[2 * 8 * 8 * 32];  // mma-layout B fragments

// ==================== CSR build ====================
__global__ void k_count(const int* __restrict__ src) {
    int e4 = blockIdx.x * blockDim.x + threadIdx.x;
    if (e4 < N_EDGES / 4) {
        int4 s = __ldg((const int4*)src + e4);
        atomicAdd(&g_cnt[s.x], 1);
        atomicAdd(&g_cnt[s.y], 1);
        atomicAdd(&g_cnt[s.z], 1);
        atomicAdd(&g_cnt[s.w], 1);
    }
}

__global__ void k_assign() {   // order-free offsets via one global counter
    int i = blockIdx.x * blockDim.x + threadIdx.x;
    if (i < N_NODES) {
        int c = g_cnt[i];
        int p = atomicAdd(&g_total, c);
        g_off[i]    = p;
        g_cursor[i] = p;
    }
}

__global__ void k_fill(const int* __restrict__ src, const int* __restrict__ dst,
                       const float* __restrict__ ew) {
    int e4 = blockIdx.x * blockDim.x + threadIdx.x;
    if (e4 < N_EDGES / 4) {
        int4   s = __ldg((const int4*)src + e4);
        int4   d = __ldg((const int4*)dst + e4);
        float4 w = __ldg((const float4*)ew + e4);
        int p;
        p = atomicAdd(&g_cursor[s.x], 1); g_csr[p] = make_int2(d.x, __float_as_int(w.x));
        p = atomicAdd(&g_cursor[s.y], 1); g_csr[p] = make_int2(d.y, __float_as_int(w.y));
        p = atomicAdd(&g_cursor[s.z], 1); g_csr[p] = make_int2(d.z, __float_as_int(w.z));
        p = atomicAdd(&g_cursor[s.w], 1); g_csr[p] = make_int2(d.w, __float_as_int(w.w));
    }
}

// ==================== prep: x16 mirror + mma-layout B fragments ====================
// B[k][j] = W[j][k].  Fragment (m16n8k16 .row.col): for lane l (grp=l>>2,q=l&3),
//   b0 = half2(W[j][k0], W[j][k0+1]),  b1 = half2(W[j][k0+8], W[j][k0+9])
//   with j = jt*8+grp, k0 = kt*16+q*2.
#define XBLOCKS ((N_NODES * D / 4 + 255) / 256)
__global__ void k_prep(const float* __restrict__ x,
                       const float* __restrict__ W1, const float* __restrict__ W2) {
    int b = blockIdx.x;
    if (b < XBLOCKS) {
        int i = b * 256 + threadIdx.x;
        if (i < N_NODES * D / 4) {
            float4 v = __ldg((const float4*)x + i);
            __half2 h0 = __floats2half2_rn(v.x, v.y);
            __half2 h1 = __floats2half2_rn(v.z, v.w);
            uint2 u;
            u.x = reinterpret_cast<const unsigned&>(h0);
            u.y = reinterpret_cast<const unsigned&>(h1);
            ((uint2*)g_x16)[i] = u;
        }
    } else {
        int t = (b - XBLOCKS) * 256 + threadIdx.x;      // 0..4095
        if (t < 2 * 8 * 8 * 32) {
            int l    = t >> 11;
            int rem  = t & 2047;
            int kt   = rem >> 8;
            int jt   = (rem >> 5) & 7;
            int lane = rem & 31;
            int grp = lane >> 2, q = lane & 3;
            int j  = jt * 8 + grp;
            int k0 = kt * 16 + q * 2;
            const float* W = l ? W2 : W1;
            __half2 h0 = __floats2half2_rn(W[j * 128 + k0],     W[j * 128 + k0 + 1]);
            __half2 h1 = __floats2half2_rn(W[j * 128 + k0 + 8], W[j * 128 + k0 + 9]);
            uint2 u;
            u.x = reinterpret_cast<const unsigned&>(h0);
            u.y = reinterpret_cast<const unsigned&>(h1);
            g_Bfrag[t] = u;
        }
    }
}

// ==================== pull aggregation (1 warp/node), fp16 out with /cnt fused ====
__global__ void __launch_bounds__(256) k_aggregate(const __half* __restrict__ xin16) {
    int node = (blockIdx.x * blockDim.x + threadIdx.x) >> 5;
    int lane = threadIdx.x & 31;
    if (node >= N_NODES) return;

    const int beg = g_off[node];
    const int n   = g_cnt[node];
    const int2* __restrict__ csr = g_csr + beg;

    float2 a0 = make_float2(0.f, 0.f), a1 = make_float2(0.f, 0.f);
    float2 a2 = make_float2(0.f, 0.f), a3 = make_float2(0.f, 0.f);

    int i = 0;
    for (; i + 4 <= n; i += 4) {
        int2 e0 = csr[i], e1 = csr[i + 1], e2 = csr[i + 2], e3 = csr[i + 3];
        __half2 h0 = __ldg((const __half2*)(xin16 + (size_t)e0.x * D) + lane);
        __half2 h1 = __ldg((const __half2*)(xin16 + (size_t)e1.x * D) + lane);
        __half2 h2 = __ldg((const __half2*)(xin16 + (size_t)e2.x * D) + lane);
        __half2 h3 = __ldg((const __half2*)(xin16 + (size_t)e3.x * D) + lane);
        float w0 = __int_as_float(e0.y), w1 = __int_as_float(e1.y);
        float w2 = __int_as_float(e2.y), w3 = __int_as_float(e3.y);
        float2 v0 = __half22float2(h0), v1 = __half22float2(h1);
        float2 v2 = __half22float2(h2), v3 = __half22float2(h3);
        a0.x += v0.x * w0; a0.y += v0.y * w0;
        a1.x += v1.x * w1; a1.y += v1.y * w1;
        a2.x += v2.x * w2; a2.y += v2.y * w2;
        a3.x += v3.x * w3; a3.y += v3.y * w3;
    }
    for (; i < n; i++) {
        int2 e0 = csr[i];
        __half2 h0 = __ldg((const __half2*)(xin16 + (size_t)e0.x * D) + lane);
        float w0 = __int_as_float(e0.y);
        float2 v0 = __half22float2(h0);
        a0.x += v0.x * w0; a0.y += v0.y * w0;
    }
    float inv = 1.0f / fmaxf((float)n, 1.0f);
    __half2 hv = __floats2half2_rn((a0.x + a1.x + a2.x + a3.x) * inv,
                                   (a0.y + a1.y + a2.y + a3.y) * inv);
    ((uint32_t*)(g_agg16 + (size_t)node * D))[lane] = reinterpret_cast<const unsigned&>(hv);
}

// ==================== HMMA GEMM: mma.sync m16n8k16, no smem ====================
// out[n][j] = relu( [x16[n] | agg16[n]] (fp16, K=128) @ W^T (fp16) + b[j] ), fp32 accum
// CTA = 256 threads = 8 warps; each warp: 16 nodes x 64 cols (8 j-tiles, 8 k-tiles)
__global__ void __launch_bounds__(256) k_gemm_mma(
        const __half* __restrict__ xin16, const __half* __restrict__ agg16,
        int wl, const float* __restrict__ bias,
        float* __restrict__ out32, __half* __restrict__ out16) {
    const int tid  = threadIdx.x;
    const int warp = tid >> 5, lane = tid & 31;
    const int grp  = lane >> 2, q = lane & 3;

    const int r0 = blockIdx.x * 128 + warp * 16 + grp;   // rows r0 and r0+8
    const int r0c = min(r0,     N_NODES - 1);
    const int r1c = min(r0 + 8, N_NODES - 1);

    const uint2* __restrict__ Bf = g_Bfrag + wl * (8 * 8 * 32);

    float c[8][4];
    #pragma unroll
    for (int jt = 0; jt < 8; jt++)
        c[jt][0] = c[jt][1] = c[jt][2] = c[jt][3] = 0.f;

    #pragma unroll
    for (int kt = 0; kt < 8; kt++) {
        const int kc = kt * 16 + q * 2;
        const __half* __restrict__ s = (kc < 64) ? xin16 : agg16;
        const int cc = kc & 63;
        uint32_t a0 = __ldg((const uint32_t*)(s + (size_t)r0c * D + cc));
        uint32_t a1 = __ldg((const uint32_t*)(s + (size_t)r1c * D + cc));
        uint32_t a2 = __ldg((const uint32_t*)(s + (size_t)r0c * D + cc + 8));
        uint32_t a3 = __ldg((const uint32_t*)(s + (size_t)r1c * D + cc + 8));
        #pragma unroll
        for (int jt = 0; jt < 8; jt++) {
            uint2 b = __ldg(Bf + ((kt * 8 + jt) * 32 + lane));
            asm volatile(
                "mma.sync.aligned.m16n8k16.row.col.f32.f16.f16.f32 "
                "{%0,%1,%2,%3}, {%4,%5,%6,%7}, {%8,%9}, {%0,%1,%2,%3};"
                : "+f"(c[jt][0]), "+f"(c[jt][1]), "+f"(c[jt][2]), "+f"(c[jt][3])
                : "r"(a0), "r"(a1), "r"(a2), "r"(a3), "r"(b.x), "r"(b.y));
        }
    }

    const bool w0 = (r0     < N_NODES);
    const bool w1 = (r0 + 8 < N_NODES);
    #pragma unroll
    for (int jt = 0; jt < 8; jt++) {
        const int j0 = jt * 8 + q * 2;
        float2 bb = __ldg((const float2*)(bias + j0));
        float v00 = fmaxf(c[jt][0] + bb.x, 0.f);
        float v01 = fmaxf(c[jt][1] + bb.y, 0.f);
        float v10 = fmaxf(c[jt][2] + bb.x, 0.f);
        float v11 = fmaxf(c[jt][3] + bb.y, 0.f);
        if (out16) {
            if (w0) {
                __half2 h = __floats2half2_rn(v00, v01);
                *(uint32_t*)(out16 + (size_t)r0 * D + j0) = reinterpret_cast<const unsigned&>(h);
            }
            if (w1) {
                __half2 h = __floats2half2_rn(v10, v11);
                *(uint32_t*)(out16 + (size_t)(r0 + 8) * D + j0) = reinterpret_cast<const unsigned&>(h);
            }
        } else {
            if (w0) *(float2*)(out32 + (size_t)r0 * D + j0)       = make_float2(v00, v01);
            if (w1) *(float2*)(out32 + (size_t)(r0 + 8) * D + j0) = make_float2(v10, v11);
        }
    }
}

// ==================== launch ====================
extern "C" void kernel_launch(void* const* d_in, const int* in_sizes, int n_in,
                              void* d_out, int out_size) {
    const float* x  = (const float*)d_in[0];
    const int*   ei = (const int*)  d_in[1];
    const float* ew = (const float*)d_in[2];
    const float* W1 = (const float*)d_in[3];
    const float* b1 = (const float*)d_in[4];
    const float* W2 = (const float*)d_in[5];
    const float* b2 = (const float*)d_in[6];
    float* out = (float*)d_out;

    const int* src = ei;
    const int* dst = ei + N_EDGES;

    void *p_cnt, *p_total, *p_x16, *p_h16, *p_agg16;
    cudaGetSymbolAddress(&p_cnt,   g_cnt);
    cudaGetSymbolAddress(&p_total, g_total);
    cudaGetSymbolAddress(&p_x16,   g_x16);
    cudaGetSymbolAddress(&p_h16,   g_h16);
    cudaGetSymbolAddress(&p_agg16, g_agg16);
    __half* x16   = (__half*)p_x16;
    __half* h16   = (__half*)p_h16;
    __half* agg16 = (__half*)p_agg16;

    cudaMemsetAsync(p_cnt,   0, N_NODES * sizeof(int));
    cudaMemsetAsync(p_total, 0, sizeof(int));

    // CSR build
    k_count <<<(N_EDGES / 4 + 255) / 256, 256>>>(src);
    k_assign<<<(N_NODES + 255) / 256, 256>>>();
    k_fill  <<<(N_EDGES / 4 + 255) / 256, 256>>>(src, dst, ew);

    // x fp16 mirror + mma-layout fp16 B fragments
    k_prep<<<XBLOCKS + 16, 256>>>(x, W1, W2);

    const int gemm_grid = (N_NODES + 127) / 128;

    // layer 1
    k_aggregate<<<(N_NODES * 32 + 255) / 256, 256>>>(x16);
    k_gemm_mma <<<gemm_grid, 256>>>(x16, agg16, 0, b1, nullptr, h16);

    // layer 2
    k_aggregate<<<(N_NODES * 32 + 255) / 256, 256>>>(h16);
    k_gemm_mma <<<gemm_grid, 256>>>(h16, agg16, 1, b2, out, nullptr);
}